// round 6
// baseline (speedup 1.0000x reference)
#include <cuda_runtime.h>
#include <math.h>

#define VOCAB 50000
#define EMB 50
#define B 256
#define S 2048
#define L1OUT (S + 6)       // 2054 conv1 outputs
#define HALF_T 1027         // outputs per half-CTA
#define WIN 1027            // T rows staged per half-CTA
#define FULL 0xffffffffu

// Device-global scratch
__device__ __align__(16) float g_T[VOCAB * 8];      // T[v][0..6]
__device__ unsigned g_cand_u[B * 16];               // per-half top-8 values (monotone u32)
__device__ int      g_cand_t[B * 16];               // per-half top-8 global indices
__device__ unsigned g_pair[B];                      // pair arrival counters (wrap at 1)
__device__ float    g_part[B];                      // per-row dense output
__device__ unsigned g_ctr = 0;                      // last-row counter (wrap at B-1)

// Order-preserving float -> u32 map (u32 compare == float compare)
__device__ __forceinline__ unsigned fmono(float f) {
    unsigned u = __float_as_uint(f);
    return (u & 0x80000000u) ? ~u : (u | 0x80000000u);
}

// ---------------------------------------------------------------------------
// Kernel A: T[v][kw] = dot(emb[v], wmean[kw]); 128 rows/CTA, coalesced staging
// ---------------------------------------------------------------------------
__global__ void __launch_bounds__(128) buildT_kernel(
    const float* __restrict__ emb, const float* __restrict__ W1) {
    __shared__ float se[128 * 51];
    __shared__ float wm[7 * 50];

    const int tid  = threadIdx.x;
    const int base = blockIdx.x * 128;
    const int nrows = min(128, VOCAB - base);

    for (int i = tid; i < 350; i += 128) {
        float s = 0.f;
        #pragma unroll
        for (int c = 0; c < 6; c++) s += W1[i * 6 + c];
        wm[i] = s * (1.f / 6.f);
    }
    const float2* e2 = (const float2*)(emb + (size_t)base * EMB);
    for (int i = tid; i < nrows * 25; i += 128) {
        int row = i / 25;
        int c2  = i - row * 25;
        float2 v = e2[row * 25 + c2];
        se[row * 51 + 2 * c2]     = v.x;
        se[row * 51 + 2 * c2 + 1] = v.y;
    }
    __syncthreads();

    if (tid >= nrows) return;
    const float* er = se + tid * 51;
    float acc[7] = {0.f, 0.f, 0.f, 0.f, 0.f, 0.f, 0.f};
    #pragma unroll 10
    for (int cin = 0; cin < EMB; cin++) {
        float e = er[cin];
        #pragma unroll
        for (int kw = 0; kw < 7; kw++) acc[kw] += e * wm[kw * EMB + cin];
    }
    float4* d = (float4*)(g_T + (size_t)(base + tid) * 8);
    d[0] = make_float4(acc[0], acc[1], acc[2], acc[3]);
    d[1] = make_float4(acc[4], acc[5], acc[6], 0.f);
}

// ---------------------------------------------------------------------------
// Kernel B: 2 CTAs (256 thr) per batch row. Each computes its half's top-8;
// second-arriving CTA of the pair merges + conv1 + tail; last row reduces.
// ---------------------------------------------------------------------------
__global__ void __launch_bounds__(256) dcnn_row_kernel(
    const int*   __restrict__ x,
    const float* __restrict__ emb,
    const float* __restrict__ W1, const float* __restrict__ b1,
    const float* __restrict__ W2, const float* __restrict__ b2,
    const float* __restrict__ Wd, const float* __restrict__ bd,
    float* __restrict__ out) {

    extern __shared__ float sm[];
    int*      stok   = (int*)sm;                  // 1028
    float*    sT     = sm + 1028;                 // 7192 (stride-7; sW1 alias later)
    unsigned* cand_u = (unsigned*)(sT + 7192);    // 64
    int*      cand_t = (int*)(cand_u + 64);       // 64
    int*      idx8s  = cand_t + 64;               // 8
    float*    s1p    = (float*)(idx8s + 8);       // 96 (16x6 zero-padded)
    float*    out2s  = s1p + 96;                  // 168 (12x14)
    int*      sflag  = (int*)(out2s + 168);       // 1
    float*    sW1    = sT;                        // alias (sT dead after phase 2)

    const int tid  = threadIdx.x;
    const int lane = tid & 31;
    const int wid  = tid >> 5;
    const int row  = blockIdx.x >> 1;
    const int h    = blockIdx.x & 1;
    const int w0   = h ? 1021 : 0;                // token window start
    const int off  = h ? 0 : -6;                  // q = t_local + kw + off
    const int* xr  = x + (size_t)row * S;

    // ---- Phase 0: stage tokens for this half's window (coalesced)
    #pragma unroll
    for (int k = 0; k < 5; k++) {
        int q = tid + k * 256;
        if (q < WIN) stok[q] = xr[w0 + q];
    }
    __syncthreads();                               // B1

    // ---- Phase 1: cooperative 8-lane T gather (4 rows / instr, 28B stores)
    const int col  = lane & 7;
    const int rsub = lane >> 3;
    #pragma unroll 4
    for (int j = 0; j < 33; j++) {
        int r = 32 * j + 4 * wid + rsub;
        if (r < WIN) {
            int tokr = stok[r];
            float v = g_T[(size_t)tokr * 8 + col];
            if (col < 7) sT[r * 7 + col] = v;
        }
    }
    __syncthreads();                               // B2

    // ---- Phase 2: excitements -> monotone u32 in registers
    unsigned evu[5];
    #pragma unroll
    for (int k = 0; k < 5; k++) {
        int tl = tid + k * 256;
        unsigned u = 0u;
        if (tl < HALF_T) {
            float s = 0.f;
            #pragma unroll
            for (int kw = 0; kw < 7; kw++) {
                int q = tl + kw + off;
                if ((unsigned)q < (unsigned)WIN) s += sT[q * 7 + kw];
            }
            u = fmono(s);
        }
        evu[k] = u;
    }
    __syncthreads();                               // B3 (sT dead)

    // ---- Phase 3a: warp-local top-8 via REDUX (value desc, global idx asc)
    #pragma unroll
    for (int r = 0; r < 8; r++) {
        unsigned bu = 0u; int bt = 0x7fffffff; int bk = 0;
        #pragma unroll
        for (int k = 0; k < 5; k++)
            if (evu[k] > bu) { bu = evu[k]; bt = h * HALF_T + tid + k * 256; bk = k; }
        unsigned m = __reduce_max_sync(FULL, bu);
        int tw = (bu == m) ? bt : 0x7fffffff;
        int tmin = __reduce_min_sync(FULL, tw);
        bool win = (bu == m) && (bt == tmin);
        #pragma unroll
        for (int k = 0; k < 5; k++)
            if (win && k == bk) evu[k] = 0u;
        if (lane == 0) { cand_u[wid * 8 + r] = m; cand_t[wid * 8 + r] = tmin; }
    }
    __syncthreads();                               // B4

    // ---- Phase 3b: warp 0 merges 64 -> half top-8, writes to global (lane 0)
    if (wid == 0) {
        unsigned cu[2]; int ct[2];
        #pragma unroll
        for (int j = 0; j < 2; j++) {
            cu[j] = cand_u[lane + 32 * j];
            ct[j] = cand_t[lane + 32 * j];
        }
        #pragma unroll
        for (int r = 0; r < 8; r++) {
            unsigned bu = 0u; int bt = 0x7fffffff; int bj = 0;
            #pragma unroll
            for (int j = 0; j < 2; j++)
                if (cu[j] > bu || (cu[j] == bu && ct[j] < bt)) {
                    bu = cu[j]; bt = ct[j]; bj = j;
                }
            unsigned m = __reduce_max_sync(FULL, bu);
            int tw = (bu == m) ? bt : 0x7fffffff;
            int tmin = __reduce_min_sync(FULL, tw);
            bool win = (bu == m) && (bt == tmin);
            #pragma unroll
            for (int j = 0; j < 2; j++)
                if (win && j == bj) cu[j] = 0u;
            if (lane == 0) {
                g_cand_u[(row * 2 + h) * 8 + r] = m;
                g_cand_t[(row * 2 + h) * 8 + r] = tmin;
            }
        }
    }
    // Pair handoff: second-arriving CTA runs the tail
    if (tid == 0) {
        __threadfence();
        unsigned old = atomicInc(&g_pair[row], 1);   // 0->1->0 self-reset
        sflag[0] = (old == 1) ? 1 : 0;
    }
    __syncthreads();                               // B5
    if (!sflag[0]) return;

    // =================== TAIL (one CTA per row) ===========================
    // Stage W1 into smem; zero s1p
    #pragma unroll
    for (int k = 0; k < 9; k++) {
        int i = tid + k * 256;
        if (i < 2100) sW1[i] = W1[i];
    }
    if (tid < 96) s1p[tid] = 0.f;

    // Warp 0: merge the pair's 16 candidates -> global ordered top-8
    if (wid == 0) {
        volatile unsigned* vu = g_cand_u;
        volatile int*      vt = g_cand_t;
        unsigned cu = (lane < 16) ? vu[row * 16 + lane] : 0u;
        int      ct = (lane < 16) ? vt[row * 16 + lane] : 0x7fffffff;
        #pragma unroll
        for (int r = 0; r < 8; r++) {
            unsigned m = __reduce_max_sync(FULL, cu);
            int tw = (cu == m) ? ct : 0x7fffffff;
            int tmin = __reduce_min_sync(FULL, tw);
            if (lane == 0) idx8s[r] = tmin;
            if (cu == m && ct == tmin) cu = 0u;
        }
    }
    __syncthreads();                               // B6

    // conv1 at the 8 selected positions: warp i -> position i
    {
        int pos = idx8s[wid];
        int tkn = -1;
        if (lane < 7) {
            int p = pos - 6 + lane;
            tkn = ((unsigned)p < (unsigned)S) ? xr[p] : -1;
        }
        float acc[6] = {0.f, 0.f, 0.f, 0.f, 0.f, 0.f};
        #pragma unroll
        for (int k = 0; k < 11; k++) {
            int rr = lane + 32 * k;
            bool ok = rr < 350;
            int rr2 = ok ? rr : 0;
            int kw = rr2 / 50;
            int cin = rr2 - kw * 50;
            int t = __shfl_sync(FULL, tkn, kw);
            float e = (ok && t >= 0) ? emb[(size_t)t * EMB + cin] : 0.f;
            #pragma unroll
            for (int c = 0; c < 6; c++) acc[c] += e * sW1[rr2 * 6 + c];
        }
        #pragma unroll
        for (int c = 0; c < 6; c++) {
            #pragma unroll
            for (int o = 16; o > 0; o >>= 1)
                acc[c] += __shfl_xor_sync(FULL, acc[c], o);   // all lanes: full sum
        }
        if (lane < 6) {
            float a = acc[0];
            a = (lane == 1) ? acc[1] : a;
            a = (lane == 2) ? acc[2] : a;
            a = (lane == 3) ? acc[3] : a;
            a = (lane == 4) ? acc[4] : a;
            a = (lane == 5) ? acc[5] : a;
            s1p[(4 + wid) * 6 + lane] = 1.f / (1.f + expf(-(a + b1[lane])));
        }
    }
    __syncthreads();                               // B7

    // ---- Warp-0 tail: conv2 -> top4 -> mean -> dense -> last-row reduce
    if (wid == 0) {
        #pragma unroll
        for (int j = 0; j < 6; j++) {
            int idx = lane + 32 * j;
            if (idx < 168) {
                int t2 = idx / 14, c2 = idx - t2 * 14;
                float a = b2[c2];
                #pragma unroll
                for (int kw2 = 0; kw2 < 5; kw2++)
                    #pragma unroll
                    for (int cin = 0; cin < 6; cin++)
                        a += s1p[(t2 + kw2) * 6 + cin] * W2[(kw2 * 6 + cin) * 14 + c2];
                out2s[idx] = a;
            }
        }
        __syncwarp();
        float e2 = 0.f;
        if (lane < 12) {
            #pragma unroll
            for (int c = 0; c < 14; c++) e2 += out2s[lane * 14 + c];
        }
        unsigned e2u = (lane < 12) ? fmono(e2) : 0u;
        int j4r[4];
        #pragma unroll
        for (int r = 0; r < 4; r++) {
            unsigned m = __reduce_max_sync(FULL, e2u);
            int tw = (e2u == m) ? lane : 63;
            int tmin = __reduce_min_sync(FULL, tw);
            j4r[r] = tmin;
            if (lane == tmin) e2u = 0u;
        }
        float mm = 0.f;
        if (lane < 14)
            mm = 0.25f * (out2s[j4r[0] * 14 + lane] + out2s[j4r[1] * 14 + lane] +
                          out2s[j4r[2] * 14 + lane] + out2s[j4r[3] * 14 + lane]) * Wd[lane];
        #pragma unroll
        for (int o = 16; o > 0; o >>= 1) mm += __shfl_xor_sync(FULL, mm, o);

        unsigned old = 0;
        if (lane == 0) {
            g_part[row] = mm + bd[0];
            __threadfence();
            old = atomicInc(&g_ctr, B - 1);        // wrap -> self-reset per replay
        }
        old = __shfl_sync(FULL, old, 0);
        if (old == B - 1) {
            __threadfence();
            float s = 0.f;
            #pragma unroll
            for (int k = 0; k < 8; k++) s += g_part[lane + 32 * k];
            #pragma unroll
            for (int o = 16; o > 0; o >>= 1) s += __shfl_xor_sync(FULL, s, o);
            if (lane == 0) out[0] = 1.f / (1.f + expf(-(s * (1.f / 256.f))));
        }
    }
}

// ---------------------------------------------------------------------------
extern "C" void kernel_launch(void* const* d_in, const int* in_sizes, int n_in,
                              void* d_out, int out_size) {
    const int*   x    = (const int*)  d_in[0];
    const float* emb  = (const float*)d_in[1];
    const float* W1   = (const float*)d_in[2];
    const float* b1   = (const float*)d_in[3];
    const float* W2   = (const float*)d_in[4];
    const float* b2   = (const float*)d_in[5];
    const float* Wd   = (const float*)d_in[6];
    const float* bd   = (const float*)d_in[7];
    float* out = (float*)d_out;

    const size_t smemB = (1028 + 7192 + 64 + 64 + 8 + 96 + 168 + 4)
                         * sizeof(float);                                 // ~34.5 KB
    cudaFuncSetAttribute(dcnn_row_kernel,
                         cudaFuncAttributeMaxDynamicSharedMemorySize, (int)smemB);

    buildT_kernel<<<(VOCAB + 127) / 128, 128>>>(emb, W1);
    dcnn_row_kernel<<<2 * B, 256, smemB>>>(x, emb, W1, b1, W2, b2, Wd, bd, out);
    (void)in_sizes; (void)n_in; (void)out_size;
}

// round 7
// speedup vs baseline: 1.1735x; 1.1735x over previous
#include <cuda_runtime.h>
#include <math.h>

#define VOCAB 50000
#define EMB 50
#define B 256
#define S 2048
#define L1OUT (S + 6)      // 2054 conv1 output length
#define NT 768             // threads per row-CTA
#define NW 24              // warps per row-CTA
#define FULL 0xffffffffu

// Scratch (device globals: the allowed scratch mechanism)
__device__ __align__(16) float g_T[VOCAB * 8];  // T[v][0..6] = dot(emb[v], wmean[kw])
__device__ float g_part[B];                      // per-batch-row dense output
__device__ unsigned g_ctr = 0;                   // last-CTA counter (wraps -> self-reset)

// Order-preserving float -> u32 map (u32 compare == float compare)
__device__ __forceinline__ unsigned fmono(float f) {
    unsigned u = __float_as_uint(f);
    return (u & 0x80000000u) ? ~u : (u | 0x80000000u);
}

// ---------------------------------------------------------------------------
// Kernel A: T[v][kw] = dot(emb[v], wmean[kw]). 128 vocab rows per CTA,
// float2-vectorized coalesced staging into smem (stride-51: conflict-free).
// ---------------------------------------------------------------------------
__global__ void __launch_bounds__(128) buildT_kernel(
    const float* __restrict__ emb, const float* __restrict__ W1) {
    __shared__ float se[128 * 51];
    __shared__ float wm[7 * 50];

    const int tid  = threadIdx.x;
    const int base = blockIdx.x * 128;
    const int nrows = min(128, VOCAB - base);

    for (int i = tid; i < 350; i += 128) {
        float s = 0.f;
        #pragma unroll
        for (int c = 0; c < 6; c++) s += W1[i * 6 + c];
        wm[i] = s * (1.f / 6.f);
    }
    const float2* e2 = (const float2*)(emb + (size_t)base * EMB);
    for (int i = tid; i < nrows * 25; i += 128) {
        int row = i / 25;
        int c2  = i - row * 25;
        float2 v = e2[row * 25 + c2];
        se[row * 51 + 2 * c2]     = v.x;
        se[row * 51 + 2 * c2 + 1] = v.y;
    }
    __syncthreads();

    if (tid >= nrows) return;
    const float* er = se + tid * 51;
    float acc[7] = {0.f, 0.f, 0.f, 0.f, 0.f, 0.f, 0.f};
    #pragma unroll 10
    for (int cin = 0; cin < EMB; cin++) {
        float e = er[cin];
        #pragma unroll
        for (int kw = 0; kw < 7; kw++) acc[kw] += e * wm[kw * EMB + cin];
    }
    float4* d = (float4*)(g_T + (size_t)(base + tid) * 8);
    d[0] = make_float4(acc[0], acc[1], acc[2], acc[3]);
    d[1] = make_float4(acc[4], acc[5], acc[6], 0.f);
}

// ---------------------------------------------------------------------------
// Kernel B: one CTA (768 thr) per batch row. Cooperative 8-lane T gather,
// REDUX-based top-8, 8-warp conv1, warp-0 tail, fused last-CTA reduction.
// ---------------------------------------------------------------------------
__global__ void __launch_bounds__(NT, 2) dcnn_row_kernel(
    const int*   __restrict__ x,
    const float* __restrict__ emb,
    const float* __restrict__ W1, const float* __restrict__ b1,
    const float* __restrict__ W2, const float* __restrict__ b2,
    const float* __restrict__ Wd, const float* __restrict__ bd,
    float* __restrict__ out) {

    extern __shared__ float sm[];
    int*      stok   = (int*)sm;                 // 2048 tokens
    float*    sT     = sm + 2048;                // 14336 (stride-7 T values)
    unsigned* cand_u = (unsigned*)(sT + 14336);  // 192
    int*      cand_t = (int*)(cand_u + 192);     // 192
    int*      idx8s  = cand_t + 192;             // 8
    float*    s1p    = (float*)(idx8s + 8);      // 96 (16x6 zero-padded)
    float*    out2s  = s1p + 96;                 // 168 (12x14)
    float*    sW1    = sT;                       // alias (sT dead after phase 2)

    const int tid  = threadIdx.x;
    const int lane = tid & 31;
    const int wid  = tid >> 5;
    const int b    = blockIdx.x;
    const int* xr  = x + (size_t)b * S;

    if (tid < 96) s1p[tid] = 0.f;

    // ---- Phase 0: stage tokens (coalesced)
    #pragma unroll
    for (int k = 0; k < 3; k++) {
        int p = tid + k * NT;
        if (p < S) stok[p] = xr[p];
    }
    __syncthreads();                              // barrier 1: tokens ready

    // ---- Phase 1: cooperative 8-lane T gather (4 rows per instruction)
    const int col  = lane & 7;
    const int rsub = lane >> 3;
    #pragma unroll
    for (int j = 0; j < 22; j++) {
        int row = j * 96 + wid * 4 + rsub;        // 24 warps x 4 rows = 96/iter
        if (row < S) {
            int tokr = stok[row];
            float v = g_T[(size_t)tokr * 8 + col];
            if (col < 7) sT[row * 7 + col] = v;   // 28 consecutive floats: no conflicts
        }
    }
    __syncthreads();                              // barrier 2: sT ready

    // ---- Phase 2: excitements -> monotone u32 in registers
    unsigned evu[3];
    #pragma unroll
    for (int k = 0; k < 3; k++) {
        int t = tid + k * NT;
        unsigned u = 0u;
        if (t < L1OUT) {
            float s = 0.f;
            #pragma unroll
            for (int kw = 0; kw < 7; kw++) {
                int p = t - 6 + kw;
                if ((unsigned)p < (unsigned)S) s += sT[p * 7 + kw];
            }
            u = fmono(s);
        }
        evu[k] = u;
    }
    __syncthreads();                              // barrier 3: sT dead

    // W1 prefetch into regs (hidden behind the redux rounds)
    float w1r[3];
    #pragma unroll
    for (int k = 0; k < 3; k++) {
        int i = tid + k * NT;
        w1r[k] = (i < 2100) ? W1[i] : 0.f;
    }

    // ---- Phase 3a: warp-local top-8 via REDUX (value desc, index asc on ties)
    #pragma unroll
    for (int r = 0; r < 8; r++) {
        unsigned bu = 0u; int bt = 0x7fffffff; int bk = 0;
        #pragma unroll
        for (int k = 0; k < 3; k++)
            if (evu[k] > bu) { bu = evu[k]; bt = tid + k * NT; bk = k; }  // k asc -> lowest t
        unsigned m = __reduce_max_sync(FULL, bu);
        int tw = (bu == m) ? bt : 0x7fffffff;
        int tmin = __reduce_min_sync(FULL, tw);
        bool win = (bu == m) && (bt == tmin);
        #pragma unroll
        for (int k = 0; k < 3; k++)
            if (win && k == bk) evu[k] = 0u;
        if (lane == 0) { cand_u[wid * 8 + r] = m; cand_t[wid * 8 + r] = tmin; }
    }
    #pragma unroll
    for (int k = 0; k < 3; k++) {                 // store staged W1
        int i = tid + k * NT;
        if (i < 2100) sW1[i] = w1r[k];
    }
    __syncthreads();                              // barrier 4

    // ---- Phase 3b: warp 0 merges 192 candidates -> global top-8 (ordered)
    if (wid == 0) {
        unsigned cu[6]; int ct[6];
        #pragma unroll
        for (int j = 0; j < 6; j++) {
            cu[j] = cand_u[lane + 32 * j];
            ct[j] = cand_t[lane + 32 * j];
        }
        #pragma unroll
        for (int r = 0; r < 8; r++) {
            unsigned bu = 0u; int bt = 0x7fffffff; int bj = 0;
            #pragma unroll
            for (int j = 0; j < 6; j++)
                if (cu[j] > bu || (cu[j] == bu && ct[j] < bt)) {
                    bu = cu[j]; bt = ct[j]; bj = j;
                }
            unsigned m = __reduce_max_sync(FULL, bu);
            int tw = (bu == m) ? bt : 0x7fffffff;
            int tmin = __reduce_min_sync(FULL, tw);
            bool win = (bu == m) && (bt == tmin);
            #pragma unroll
            for (int j = 0; j < 6; j++)
                if (win && j == bj) cu[j] = 0u;
            if (lane == 0) idx8s[r] = tmin;
        }
    }
    __syncthreads();                              // barrier 5

    // ---- Phase 4: conv1 at the 8 selected positions (warp i -> position i)
    if (wid < 8) {
        int pos = idx8s[wid];
        int tkn = -1;
        if (lane < 7) {
            int p = pos - 6 + lane;
            tkn = ((unsigned)p < (unsigned)S) ? stok[p] : -1;
        }
        float acc[6] = {0.f, 0.f, 0.f, 0.f, 0.f, 0.f};
        #pragma unroll
        for (int k = 0; k < 11; k++) {
            int rr = lane + 32 * k;
            bool ok = rr < 350;
            int rr2 = ok ? rr : 0;
            int kw = rr2 / 50;
            int cin = rr2 - kw * 50;
            int t = __shfl_sync(FULL, tkn, kw);
            float e = (ok && t >= 0) ? emb[(size_t)t * EMB + cin] : 0.f;
            #pragma unroll
            for (int c = 0; c < 6; c++) acc[c] += e * sW1[rr2 * 6 + c];
        }
        #pragma unroll
        for (int c = 0; c < 6; c++) {
            #pragma unroll
            for (int o = 16; o > 0; o >>= 1)
                acc[c] += __shfl_xor_sync(FULL, acc[c], o);   // all lanes: full sum
        }
        if (lane < 6) {
            float a = acc[0];
            a = (lane == 1) ? acc[1] : a;
            a = (lane == 2) ? acc[2] : a;
            a = (lane == 3) ? acc[3] : a;
            a = (lane == 4) ? acc[4] : a;
            a = (lane == 5) ? acc[5] : a;
            s1p[(4 + wid) * 6 + lane] = 1.f / (1.f + expf(-(a + b1[lane])));
        }
    }
    __syncthreads();                              // barrier 6 (last)

    // ---- Tail: warp 0 only
    if (wid == 0) {
        // conv2 -> out2s[12x14]
        #pragma unroll
        for (int j = 0; j < 6; j++) {
            int idx = lane + 32 * j;
            if (idx < 168) {
                int t2 = idx / 14, c2 = idx - t2 * 14;
                float a = b2[c2];
                #pragma unroll
                for (int kw2 = 0; kw2 < 5; kw2++)
                    #pragma unroll
                    for (int cin = 0; cin < 6; cin++)
                        a += s1p[(t2 + kw2) * 6 + cin] * W2[(kw2 * 6 + cin) * 14 + c2];
                out2s[idx] = a;
            }
        }
        __syncwarp();
        // top-4 of channel-sums via REDUX (lane t2 owns row t2)
        float e2 = 0.f;
        if (lane < 12) {
            #pragma unroll
            for (int c = 0; c < 14; c++) e2 += out2s[lane * 14 + c];
        }
        unsigned e2u = (lane < 12) ? fmono(e2) : 0u;
        int j4r[4];
        #pragma unroll
        for (int r = 0; r < 4; r++) {
            unsigned m = __reduce_max_sync(FULL, e2u);
            int tw = (e2u == m) ? lane : 63;
            int tmin = __reduce_min_sync(FULL, tw);
            j4r[r] = tmin;
            if (lane == tmin) e2u = 0u;
        }
        float mm = 0.f;
        if (lane < 14)
            mm = 0.25f * (out2s[j4r[0] * 14 + lane] + out2s[j4r[1] * 14 + lane] +
                          out2s[j4r[2] * 14 + lane] + out2s[j4r[3] * 14 + lane]) * Wd[lane];
        #pragma unroll
        for (int o = 16; o > 0; o >>= 1) mm += __shfl_xor_sync(FULL, mm, o);

        unsigned old = 0;
        if (lane == 0) {
            g_part[b] = mm + bd[0];
            __threadfence();
            old = atomicInc(&g_ctr, B - 1);       // wraps -> self-reset each replay
        }
        old = __shfl_sync(FULL, old, 0);
        if (old == B - 1) {
            __threadfence();                      // acquire side
            float s = 0.f;
            #pragma unroll
            for (int k = 0; k < 8; k++) s += g_part[lane + 32 * k];
            #pragma unroll
            for (int o = 16; o > 0; o >>= 1) s += __shfl_xor_sync(FULL, s, o);
            if (lane == 0) out[0] = 1.f / (1.f + expf(-(s * (1.f / 256.f))));
        }
    }
}

// ---------------------------------------------------------------------------
extern "C" void kernel_launch(void* const* d_in, const int* in_sizes, int n_in,
                              void* d_out, int out_size) {
    const int*   x    = (const int*)  d_in[0];
    const float* emb  = (const float*)d_in[1];
    const float* W1   = (const float*)d_in[2];
    const float* b1   = (const float*)d_in[3];
    const float* W2   = (const float*)d_in[4];
    const float* b2   = (const float*)d_in[5];
    const float* Wd   = (const float*)d_in[6];
    const float* bd   = (const float*)d_in[7];
    float* out = (float*)d_out;

    const size_t smemB = (2048 + 14336 + 192 + 192 + 8 + 96 + 168)
                         * sizeof(float);                                  // 68160 B
    cudaFuncSetAttribute(dcnn_row_kernel,
                         cudaFuncAttributeMaxDynamicSharedMemorySize, (int)smemB);

    buildT_kernel<<<(VOCAB + 127) / 128, 128>>>(emb, W1);
    dcnn_row_kernel<<<B, NT, smemB>>>(x, emb, W1, b1, W2, b2, Wd, bd, out);
    (void)in_sizes; (void)n_in; (void)out_size;
}